// round 15
// baseline (speedup 1.0000x reference)
#include <cuda_runtime.h>
#include <cstdint>

// HashEncoding: 5-level instant-NGP trilinear hash grid lookup.
//   N = in_sizes[0]/3 points, tables [5, 2^20, 4] fp32, out [N, 20] fp32.
// R15 = R13 champion, block 512 (same 64 warps/SM, half the CTAs).
//   - one thread per (point, level), n-major -> coalesced output stores
//   - x-corner pairing: hash = px ^ (y*PI2 ^ z*PI3), px un-multiplied, so for
//     even bx corners (0,y,z)/(1,y,z) sit at {i, i^1} -> one 32B v8 load
//   - L1::no_allocate on all table gathers (random, never L1-hit: skip fills)
//   - L2 evict_last on tables, streaming .cs stores on output
//   - 32 regs, 4 blocks x 512 / SM

#define HASH_BITS   20
#define HASH_MASK   ((1u << HASH_BITS) - 1u)
#define NUM_LEVELS  5
#define PI2 19349663u
#define PI3 83492791u

__device__ __forceinline__ void ld_pair(const float4* p, float4& lo, float4& hi) {
    asm("ld.global.nc.L1::no_allocate.L2::evict_last.v8.b32 "
        "{%0,%1,%2,%3,%4,%5,%6,%7}, [%8];"
        : "=f"(lo.x), "=f"(lo.y), "=f"(lo.z), "=f"(lo.w),
          "=f"(hi.x), "=f"(hi.y), "=f"(hi.z), "=f"(hi.w)
        : "l"(p));
}

__device__ __forceinline__ float4 ld_tab(const float4* p, unsigned long long pol) {
    float4 v;
    asm("ld.global.nc.L1::no_allocate.L2::cache_hint.v4.f32 "
        "{%0,%1,%2,%3}, [%4], %5;"
        : "=f"(v.x), "=f"(v.y), "=f"(v.z), "=f"(v.w) : "l"(p), "l"(pol));
    return v;
}

__device__ __forceinline__ void st_stream(float4* p, float4 v) {
    asm volatile("st.global.cs.v4.f32 [%0], {%1,%2,%3,%4};"
                 :: "l"(p), "f"(v.x), "f"(v.y), "f"(v.z), "f"(v.w) : "memory");
}

__global__ void __launch_bounds__(512, 4)
hashenc_kernel(const float* __restrict__ x,
               const float4* __restrict__ tables,
               float4* __restrict__ out,
               int n_points)
{
    int tid = blockIdx.x * blockDim.x + threadIdx.x;
    int total = n_points * NUM_LEVELS;
    if (tid >= total) return;

    int n = tid / NUM_LEVELS;
    int l = tid - n * NUM_LEVELS;

    unsigned long long pol;
    asm("createpolicy.fractional.L2::evict_last.b64 %0, 1.0;" : "=l"(pol));

    float cx = __ldg(x + n * 3 + 0);
    float cy = __ldg(x + n * 3 + 1);
    float cz = __ldg(x + n * 3 + 2);

    // x01 = (x + 2) / 4 ; loc = x01 * gs - 0.5 ; gs = 128 << l
    float gs = (float)(128 << l);
    float lx = (cx + 2.0f) * 0.25f * gs - 0.5f;
    float ly = (cy + 2.0f) * 0.25f * gs - 0.5f;
    float lz = (cz + 2.0f) * 0.25f * gs - 0.5f;

    float fx = floorf(lx), fy = floorf(ly), fz = floorf(lz);
    float wx1 = lx - fx, wy1 = ly - fy, wz1 = lz - fz;
    float wx0 = 1.0f - wx1, wy0 = 1.0f - wy1, wz0 = 1.0f - wz1;

    unsigned bx = (unsigned)(int)fx;
    unsigned by = (unsigned)(int)fy;
    unsigned bz = (unsigned)(int)fz;

    unsigned hy0 = by * PI2;
    unsigned hz0 = bz * PI3;
    unsigned dy  = hy0 ^ ((by + 1u) * PI2);
    unsigned dz  = hz0 ^ ((bz + 1u) * PI3);

    const float4* __restrict__ tab = tables + ((size_t)l << HASH_BITS);

    unsigned h000 = bx ^ hy0 ^ hz0;
    unsigned i000 = h000 & HASH_MASK;
    unsigned i001 = (h000 ^ dz) & HASH_MASK;
    unsigned i010 = (h000 ^ dy) & HASH_MASK;
    unsigned i011 = (h000 ^ dy ^ dz) & HASH_MASK;

    // weights, same association as reference: (wx*wy)*wz
    float w000 = (wx0 * wy0) * wz0;
    float w001 = (wx0 * wy0) * wz1;
    float w010 = (wx0 * wy1) * wz0;
    float w011 = (wx0 * wy1) * wz1;
    float w100 = (wx1 * wy0) * wz0;
    float w101 = (wx1 * wy0) * wz1;
    float w110 = (wx1 * wy1) * wz0;
    float w111 = (wx1 * wy1) * wz1;

    float ax, ay, az, aw;

    if ((bx & 1u) == 0u) {
        // Even bx: x0/x1 corners table-adjacent (i, i^1). 4 x 32B loads.
        float4 a0, b0, a1, b1, a2, b2, a3, b3;
        ld_pair(tab + (i000 & ~1u), a0, b0);
        ld_pair(tab + (i001 & ~1u), a1, b1);
        ld_pair(tab + (i010 & ~1u), a2, b2);
        ld_pair(tab + (i011 & ~1u), a3, b3);

        float wl0 = (i000 & 1u) ? w100 : w000, wh0 = (i000 & 1u) ? w000 : w100;
        float wl1 = (i001 & 1u) ? w101 : w001, wh1 = (i001 & 1u) ? w001 : w101;
        float wl2 = (i010 & 1u) ? w110 : w010, wh2 = (i010 & 1u) ? w010 : w110;
        float wl3 = (i011 & 1u) ? w111 : w011, wh3 = (i011 & 1u) ? w011 : w111;

        ax = a0.x * wl0; ay = a0.y * wl0; az = a0.z * wl0; aw = a0.w * wl0;
        ax = fmaf(b0.x, wh0, ax); ay = fmaf(b0.y, wh0, ay); az = fmaf(b0.z, wh0, az); aw = fmaf(b0.w, wh0, aw);
        ax = fmaf(a1.x, wl1, ax); ay = fmaf(a1.y, wl1, ay); az = fmaf(a1.z, wl1, az); aw = fmaf(a1.w, wl1, aw);
        ax = fmaf(b1.x, wh1, ax); ay = fmaf(b1.y, wh1, ay); az = fmaf(b1.z, wh1, az); aw = fmaf(b1.w, wh1, aw);
        ax = fmaf(a2.x, wl2, ax); ay = fmaf(a2.y, wl2, ay); az = fmaf(a2.z, wl2, az); aw = fmaf(a2.w, wl2, aw);
        ax = fmaf(b2.x, wh2, ax); ay = fmaf(b2.y, wh2, ay); az = fmaf(b2.z, wh2, az); aw = fmaf(b2.w, wh2, aw);
        ax = fmaf(a3.x, wl3, ax); ay = fmaf(a3.y, wl3, ay); az = fmaf(a3.z, wl3, az); aw = fmaf(a3.w, wl3, aw);
        ax = fmaf(b3.x, wh3, ax); ay = fmaf(b3.y, wh3, ay); az = fmaf(b3.z, wh3, az); aw = fmaf(b3.w, wh3, aw);
    } else {
        // Odd bx: no adjacency; 8 x 16B gathers with evict_last policy.
        unsigned h100 = h000 ^ bx ^ (bx + 1u);
        unsigned i100 = h100 & HASH_MASK;
        unsigned i101 = (h100 ^ dz) & HASH_MASK;
        unsigned i110 = (h100 ^ dy) & HASH_MASK;
        unsigned i111 = (h100 ^ dy ^ dz) & HASH_MASK;

        float4 v000 = ld_tab(tab + i000, pol);
        float4 v001 = ld_tab(tab + i001, pol);
        float4 v010 = ld_tab(tab + i010, pol);
        float4 v011 = ld_tab(tab + i011, pol);
        float4 v100 = ld_tab(tab + i100, pol);
        float4 v101 = ld_tab(tab + i101, pol);
        float4 v110 = ld_tab(tab + i110, pol);
        float4 v111 = ld_tab(tab + i111, pol);

        ax = v000.x * w000; ay = v000.y * w000; az = v000.z * w000; aw = v000.w * w000;
        ax = fmaf(v001.x, w001, ax); ay = fmaf(v001.y, w001, ay); az = fmaf(v001.z, w001, az); aw = fmaf(v001.w, w001, aw);
        ax = fmaf(v010.x, w010, ax); ay = fmaf(v010.y, w010, ay); az = fmaf(v010.z, w010, az); aw = fmaf(v010.w, w010, aw);
        ax = fmaf(v011.x, w011, ax); ay = fmaf(v011.y, w011, ay); az = fmaf(v011.z, w011, az); aw = fmaf(v011.w, w011, aw);
        ax = fmaf(v100.x, w100, ax); ay = fmaf(v100.y, w100, ay); az = fmaf(v100.z, w100, az); aw = fmaf(v100.w, w100, aw);
        ax = fmaf(v101.x, w101, ax); ay = fmaf(v101.y, w101, ay); az = fmaf(v101.z, w101, az); aw = fmaf(v101.w, w101, aw);
        ax = fmaf(v110.x, w110, ax); ay = fmaf(v110.y, w110, ay); az = fmaf(v110.z, w110, az); aw = fmaf(v110.w, w110, aw);
        ax = fmaf(v111.x, w111, ax); ay = fmaf(v111.y, w111, ay); az = fmaf(v111.z, w111, az); aw = fmaf(v111.w, w111, aw);
    }

    float4 r;
    r.x = ax * 10.0f;
    r.y = ay * 10.0f;
    r.z = az * 10.0f;
    r.w = aw * 10.0f;
    st_stream(out + (size_t)n * NUM_LEVELS + l, r);   // == out + tid, coalesced
}

extern "C" void kernel_launch(void* const* d_in, const int* in_sizes, int n_in,
                              void* d_out, int out_size)
{
    const float*  x      = (const float*)d_in[0];
    const float4* tables = (const float4*)d_in[1];
    float4*       out    = (float4*)d_out;

    int n_points = in_sizes[0] / 3;
    int total = n_points * NUM_LEVELS;
    int block = 512;
    int grid = (total + block - 1) / block;
    hashenc_kernel<<<grid, block>>>(x, tables, out, n_points);
}

// round 16
// speedup vs baseline: 1.0035x; 1.0035x over previous
#include <cuda_runtime.h>
#include <cstdint>

// HashEncoding: 5-level instant-NGP trilinear hash grid lookup.  FINAL (R13).
//   N = in_sizes[0]/3 points, tables [5, 2^20, 4] fp32, out [N, 20] fp32.
// Champion kernel, ~128.7us (~98% of the L1-sector roofline):
//   - one thread per (point, level), n-major -> fully coalesced output stores
//   - x-corner pairing: hash = px ^ (y*PI2 ^ z*PI3); px enters un-multiplied,
//     so for even bx the corners (0,y,z)/(1,y,z) sit at {i, i^1} = one
//     32B-aligned pair -> one v8.b32 load. 8 gathers -> 4 for half the
//     threads (avg 6 sectors/item, algorithmic minimum: odd bx has no
//     adjacency since bx^(bx+1) != 1).
//   - L1::no_allocate on table gathers (random over 80MB, never L1-hit:
//     skip useless fills, keep x-coords resident)
//   - L2 evict_last on all table loads; streaming .cs stores on output
//   - 32 regs, 8 blocks x 256 / SM (64 warps/SM)

#define HASH_BITS   20
#define HASH_MASK   ((1u << HASH_BITS) - 1u)
#define NUM_LEVELS  5
#define PI2 19349663u
#define PI3 83492791u

__device__ __forceinline__ void ld_pair(const float4* p, float4& lo, float4& hi) {
    asm("ld.global.nc.L1::no_allocate.L2::evict_last.v8.b32 "
        "{%0,%1,%2,%3,%4,%5,%6,%7}, [%8];"
        : "=f"(lo.x), "=f"(lo.y), "=f"(lo.z), "=f"(lo.w),
          "=f"(hi.x), "=f"(hi.y), "=f"(hi.z), "=f"(hi.w)
        : "l"(p));
}

__device__ __forceinline__ float4 ld_tab(const float4* p, unsigned long long pol) {
    float4 v;
    asm("ld.global.nc.L1::no_allocate.L2::cache_hint.v4.f32 "
        "{%0,%1,%2,%3}, [%4], %5;"
        : "=f"(v.x), "=f"(v.y), "=f"(v.z), "=f"(v.w) : "l"(p), "l"(pol));
    return v;
}

__device__ __forceinline__ void st_stream(float4* p, float4 v) {
    asm volatile("st.global.cs.v4.f32 [%0], {%1,%2,%3,%4};"
                 :: "l"(p), "f"(v.x), "f"(v.y), "f"(v.z), "f"(v.w) : "memory");
}

__global__ void __launch_bounds__(256, 8)
hashenc_kernel(const float* __restrict__ x,
               const float4* __restrict__ tables,
               float4* __restrict__ out,
               int n_points)
{
    int tid = blockIdx.x * blockDim.x + threadIdx.x;
    int total = n_points * NUM_LEVELS;
    if (tid >= total) return;

    int n = tid / NUM_LEVELS;
    int l = tid - n * NUM_LEVELS;

    unsigned long long pol;
    asm("createpolicy.fractional.L2::evict_last.b64 %0, 1.0;" : "=l"(pol));

    float cx = __ldg(x + n * 3 + 0);
    float cy = __ldg(x + n * 3 + 1);
    float cz = __ldg(x + n * 3 + 2);

    // x01 = (x + 2) / 4 ; loc = x01 * gs - 0.5 ; gs = 128 << l
    float gs = (float)(128 << l);
    float lx = (cx + 2.0f) * 0.25f * gs - 0.5f;
    float ly = (cy + 2.0f) * 0.25f * gs - 0.5f;
    float lz = (cz + 2.0f) * 0.25f * gs - 0.5f;

    float fx = floorf(lx), fy = floorf(ly), fz = floorf(lz);
    float wx1 = lx - fx, wy1 = ly - fy, wz1 = lz - fz;
    float wx0 = 1.0f - wx1, wy0 = 1.0f - wy1, wz0 = 1.0f - wz1;

    unsigned bx = (unsigned)(int)fx;
    unsigned by = (unsigned)(int)fy;
    unsigned bz = (unsigned)(int)fz;

    unsigned hy0 = by * PI2;
    unsigned hz0 = bz * PI3;
    unsigned dy  = hy0 ^ ((by + 1u) * PI2);
    unsigned dz  = hz0 ^ ((bz + 1u) * PI3);

    const float4* __restrict__ tab = tables + ((size_t)l << HASH_BITS);

    unsigned h000 = bx ^ hy0 ^ hz0;
    unsigned i000 = h000 & HASH_MASK;
    unsigned i001 = (h000 ^ dz) & HASH_MASK;
    unsigned i010 = (h000 ^ dy) & HASH_MASK;
    unsigned i011 = (h000 ^ dy ^ dz) & HASH_MASK;

    // weights, same association as reference: (wx*wy)*wz
    float w000 = (wx0 * wy0) * wz0;
    float w001 = (wx0 * wy0) * wz1;
    float w010 = (wx0 * wy1) * wz0;
    float w011 = (wx0 * wy1) * wz1;
    float w100 = (wx1 * wy0) * wz0;
    float w101 = (wx1 * wy0) * wz1;
    float w110 = (wx1 * wy1) * wz0;
    float w111 = (wx1 * wy1) * wz1;

    float ax, ay, az, aw;

    if ((bx & 1u) == 0u) {
        // Even bx: x0/x1 corners table-adjacent (i, i^1). 4 x 32B loads.
        float4 a0, b0, a1, b1, a2, b2, a3, b3;
        ld_pair(tab + (i000 & ~1u), a0, b0);
        ld_pair(tab + (i001 & ~1u), a1, b1);
        ld_pair(tab + (i010 & ~1u), a2, b2);
        ld_pair(tab + (i011 & ~1u), a3, b3);

        float wl0 = (i000 & 1u) ? w100 : w000, wh0 = (i000 & 1u) ? w000 : w100;
        float wl1 = (i001 & 1u) ? w101 : w001, wh1 = (i001 & 1u) ? w001 : w101;
        float wl2 = (i010 & 1u) ? w110 : w010, wh2 = (i010 & 1u) ? w010 : w110;
        float wl3 = (i011 & 1u) ? w111 : w011, wh3 = (i011 & 1u) ? w011 : w111;

        ax = a0.x * wl0; ay = a0.y * wl0; az = a0.z * wl0; aw = a0.w * wl0;
        ax = fmaf(b0.x, wh0, ax); ay = fmaf(b0.y, wh0, ay); az = fmaf(b0.z, wh0, az); aw = fmaf(b0.w, wh0, aw);
        ax = fmaf(a1.x, wl1, ax); ay = fmaf(a1.y, wl1, ay); az = fmaf(a1.z, wl1, az); aw = fmaf(a1.w, wl1, aw);
        ax = fmaf(b1.x, wh1, ax); ay = fmaf(b1.y, wh1, ay); az = fmaf(b1.z, wh1, az); aw = fmaf(b1.w, wh1, aw);
        ax = fmaf(a2.x, wl2, ax); ay = fmaf(a2.y, wl2, ay); az = fmaf(a2.z, wl2, az); aw = fmaf(a2.w, wl2, aw);
        ax = fmaf(b2.x, wh2, ax); ay = fmaf(b2.y, wh2, ay); az = fmaf(b2.z, wh2, az); aw = fmaf(b2.w, wh2, aw);
        ax = fmaf(a3.x, wl3, ax); ay = fmaf(a3.y, wl3, ay); az = fmaf(a3.z, wl3, az); aw = fmaf(a3.w, wl3, aw);
        ax = fmaf(b3.x, wh3, ax); ay = fmaf(b3.y, wh3, ay); az = fmaf(b3.z, wh3, az); aw = fmaf(b3.w, wh3, aw);
    } else {
        // Odd bx: no adjacency; 8 x 16B gathers with evict_last policy.
        unsigned h100 = h000 ^ bx ^ (bx + 1u);
        unsigned i100 = h100 & HASH_MASK;
        unsigned i101 = (h100 ^ dz) & HASH_MASK;
        unsigned i110 = (h100 ^ dy) & HASH_MASK;
        unsigned i111 = (h100 ^ dy ^ dz) & HASH_MASK;

        float4 v000 = ld_tab(tab + i000, pol);
        float4 v001 = ld_tab(tab + i001, pol);
        float4 v010 = ld_tab(tab + i010, pol);
        float4 v011 = ld_tab(tab + i011, pol);
        float4 v100 = ld_tab(tab + i100, pol);
        float4 v101 = ld_tab(tab + i101, pol);
        float4 v110 = ld_tab(tab + i110, pol);
        float4 v111 = ld_tab(tab + i111, pol);

        ax = v000.x * w000; ay = v000.y * w000; az = v000.z * w000; aw = v000.w * w000;
        ax = fmaf(v001.x, w001, ax); ay = fmaf(v001.y, w001, ay); az = fmaf(v001.z, w001, az); aw = fmaf(v001.w, w001, aw);
        ax = fmaf(v010.x, w010, ax); ay = fmaf(v010.y, w010, ay); az = fmaf(v010.z, w010, az); aw = fmaf(v010.w, w010, aw);
        ax = fmaf(v011.x, w011, ax); ay = fmaf(v011.y, w011, ay); az = fmaf(v011.z, w011, az); aw = fmaf(v011.w, w011, aw);
        ax = fmaf(v100.x, w100, ax); ay = fmaf(v100.y, w100, ay); az = fmaf(v100.z, w100, az); aw = fmaf(v100.w, w100, aw);
        ax = fmaf(v101.x, w101, ax); ay = fmaf(v101.y, w101, ay); az = fmaf(v101.z, w101, az); aw = fmaf(v101.w, w101, aw);
        ax = fmaf(v110.x, w110, ax); ay = fmaf(v110.y, w110, ay); az = fmaf(v110.z, w110, az); aw = fmaf(v110.w, w110, aw);
        ax = fmaf(v111.x, w111, ax); ay = fmaf(v111.y, w111, ay); az = fmaf(v111.z, w111, az); aw = fmaf(v111.w, w111, aw);
    }

    float4 r;
    r.x = ax * 10.0f;
    r.y = ay * 10.0f;
    r.z = az * 10.0f;
    r.w = aw * 10.0f;
    st_stream(out + (size_t)n * NUM_LEVELS + l, r);   // == out + tid, coalesced
}

extern "C" void kernel_launch(void* const* d_in, const int* in_sizes, int n_in,
                              void* d_out, int out_size)
{
    const float*  x      = (const float*)d_in[0];
    const float4* tables = (const float4*)d_in[1];
    float4*       out    = (float4*)d_out;

    int n_points = in_sizes[0] / 3;
    int total = n_points * NUM_LEVELS;
    int block = 256;
    int grid = (total + block - 1) / block;
    hashenc_kernel<<<grid, block>>>(x, tables, out, n_points);
}

// round 17
// speedup vs baseline: 1.0087x; 1.0052x over previous
#include <cuda_runtime.h>
#include <cstdint>

// HashEncoding: 5-level instant-NGP trilinear hash grid lookup.  FINAL (R13).
//   N = in_sizes[0]/3 points, tables [5, 2^20, 4] fp32, out [N, 20] fp32.
// Champion kernel, ~128.7us (~98% of the L1-sector roofline):
//   - one thread per (point, level), n-major -> fully coalesced output stores
//   - x-corner pairing: hash = px ^ (y*PI2 ^ z*PI3); px enters un-multiplied,
//     so for even bx the corners (0,y,z)/(1,y,z) sit at {i, i^1} = one
//     32B-aligned pair -> one v8.b32 load. 8 gathers -> 4 for half the
//     threads (avg 6 sectors/item is the algorithmic minimum: for odd bx,
//     bx^(bx+1) >= 3, so its corners always land in different 32B sectors).
//   - L1::no_allocate on table gathers (random over 80MB, never L1-hit:
//     skip useless fills, keep x-coords resident)
//   - L2 evict_last on all table loads; streaming .cs stores on output
//   - 32 regs, 8 blocks x 256 / SM (64 warps/SM)

#define HASH_BITS   20
#define HASH_MASK   ((1u << HASH_BITS) - 1u)
#define NUM_LEVELS  5
#define PI2 19349663u
#define PI3 83492791u

__device__ __forceinline__ void ld_pair(const float4* p, float4& lo, float4& hi) {
    asm("ld.global.nc.L1::no_allocate.L2::evict_last.v8.b32 "
        "{%0,%1,%2,%3,%4,%5,%6,%7}, [%8];"
        : "=f"(lo.x), "=f"(lo.y), "=f"(lo.z), "=f"(lo.w),
          "=f"(hi.x), "=f"(hi.y), "=f"(hi.z), "=f"(hi.w)
        : "l"(p));
}

__device__ __forceinline__ float4 ld_tab(const float4* p, unsigned long long pol) {
    float4 v;
    asm("ld.global.nc.L1::no_allocate.L2::cache_hint.v4.f32 "
        "{%0,%1,%2,%3}, [%4], %5;"
        : "=f"(v.x), "=f"(v.y), "=f"(v.z), "=f"(v.w) : "l"(p), "l"(pol));
    return v;
}

__device__ __forceinline__ void st_stream(float4* p, float4 v) {
    asm volatile("st.global.cs.v4.f32 [%0], {%1,%2,%3,%4};"
                 :: "l"(p), "f"(v.x), "f"(v.y), "f"(v.z), "f"(v.w) : "memory");
}

__global__ void __launch_bounds__(256, 8)
hashenc_kernel(const float* __restrict__ x,
               const float4* __restrict__ tables,
               float4* __restrict__ out,
               int n_points)
{
    int tid = blockIdx.x * blockDim.x + threadIdx.x;
    int total = n_points * NUM_LEVELS;
    if (tid >= total) return;

    int n = tid / NUM_LEVELS;
    int l = tid - n * NUM_LEVELS;

    unsigned long long pol;
    asm("createpolicy.fractional.L2::evict_last.b64 %0, 1.0;" : "=l"(pol));

    float cx = __ldg(x + n * 3 + 0);
    float cy = __ldg(x + n * 3 + 1);
    float cz = __ldg(x + n * 3 + 2);

    // x01 = (x + 2) / 4 ; loc = x01 * gs - 0.5 ; gs = 128 << l
    float gs = (float)(128 << l);
    float lx = (cx + 2.0f) * 0.25f * gs - 0.5f;
    float ly = (cy + 2.0f) * 0.25f * gs - 0.5f;
    float lz = (cz + 2.0f) * 0.25f * gs - 0.5f;

    float fx = floorf(lx), fy = floorf(ly), fz = floorf(lz);
    float wx1 = lx - fx, wy1 = ly - fy, wz1 = lz - fz;
    float wx0 = 1.0f - wx1, wy0 = 1.0f - wy1, wz0 = 1.0f - wz1;

    unsigned bx = (unsigned)(int)fx;
    unsigned by = (unsigned)(int)fy;
    unsigned bz = (unsigned)(int)fz;

    unsigned hy0 = by * PI2;
    unsigned hz0 = bz * PI3;
    unsigned dy  = hy0 ^ ((by + 1u) * PI2);
    unsigned dz  = hz0 ^ ((bz + 1u) * PI3);

    const float4* __restrict__ tab = tables + ((size_t)l << HASH_BITS);

    unsigned h000 = bx ^ hy0 ^ hz0;
    unsigned i000 = h000 & HASH_MASK;
    unsigned i001 = (h000 ^ dz) & HASH_MASK;
    unsigned i010 = (h000 ^ dy) & HASH_MASK;
    unsigned i011 = (h000 ^ dy ^ dz) & HASH_MASK;

    // weights, same association as reference: (wx*wy)*wz
    float w000 = (wx0 * wy0) * wz0;
    float w001 = (wx0 * wy0) * wz1;
    float w010 = (wx0 * wy1) * wz0;
    float w011 = (wx0 * wy1) * wz1;
    float w100 = (wx1 * wy0) * wz0;
    float w101 = (wx1 * wy0) * wz1;
    float w110 = (wx1 * wy1) * wz0;
    float w111 = (wx1 * wy1) * wz1;

    float ax, ay, az, aw;

    if ((bx & 1u) == 0u) {
        // Even bx: x0/x1 corners table-adjacent (i, i^1). 4 x 32B loads.
        float4 a0, b0, a1, b1, a2, b2, a3, b3;
        ld_pair(tab + (i000 & ~1u), a0, b0);
        ld_pair(tab + (i001 & ~1u), a1, b1);
        ld_pair(tab + (i010 & ~1u), a2, b2);
        ld_pair(tab + (i011 & ~1u), a3, b3);

        float wl0 = (i000 & 1u) ? w100 : w000, wh0 = (i000 & 1u) ? w000 : w100;
        float wl1 = (i001 & 1u) ? w101 : w001, wh1 = (i001 & 1u) ? w001 : w101;
        float wl2 = (i010 & 1u) ? w110 : w010, wh2 = (i010 & 1u) ? w010 : w110;
        float wl3 = (i011 & 1u) ? w111 : w011, wh3 = (i011 & 1u) ? w011 : w111;

        ax = a0.x * wl0; ay = a0.y * wl0; az = a0.z * wl0; aw = a0.w * wl0;
        ax = fmaf(b0.x, wh0, ax); ay = fmaf(b0.y, wh0, ay); az = fmaf(b0.z, wh0, az); aw = fmaf(b0.w, wh0, aw);
        ax = fmaf(a1.x, wl1, ax); ay = fmaf(a1.y, wl1, ay); az = fmaf(a1.z, wl1, az); aw = fmaf(a1.w, wl1, aw);
        ax = fmaf(b1.x, wh1, ax); ay = fmaf(b1.y, wh1, ay); az = fmaf(b1.z, wh1, az); aw = fmaf(b1.w, wh1, aw);
        ax = fmaf(a2.x, wl2, ax); ay = fmaf(a2.y, wl2, ay); az = fmaf(a2.z, wl2, az); aw = fmaf(a2.w, wl2, aw);
        ax = fmaf(b2.x, wh2, ax); ay = fmaf(b2.y, wh2, ay); az = fmaf(b2.z, wh2, az); aw = fmaf(b2.w, wh2, aw);
        ax = fmaf(a3.x, wl3, ax); ay = fmaf(a3.y, wl3, ay); az = fmaf(a3.z, wl3, az); aw = fmaf(a3.w, wl3, aw);
        ax = fmaf(b3.x, wh3, ax); ay = fmaf(b3.y, wh3, ay); az = fmaf(b3.z, wh3, az); aw = fmaf(b3.w, wh3, aw);
    } else {
        // Odd bx: no adjacency; 8 x 16B gathers with evict_last policy.
        unsigned h100 = h000 ^ bx ^ (bx + 1u);
        unsigned i100 = h100 & HASH_MASK;
        unsigned i101 = (h100 ^ dz) & HASH_MASK;
        unsigned i110 = (h100 ^ dy) & HASH_MASK;
        unsigned i111 = (h100 ^ dy ^ dz) & HASH_MASK;

        float4 v000 = ld_tab(tab + i000, pol);
        float4 v001 = ld_tab(tab + i001, pol);
        float4 v010 = ld_tab(tab + i010, pol);
        float4 v011 = ld_tab(tab + i011, pol);
        float4 v100 = ld_tab(tab + i100, pol);
        float4 v101 = ld_tab(tab + i101, pol);
        float4 v110 = ld_tab(tab + i110, pol);
        float4 v111 = ld_tab(tab + i111, pol);

        ax = v000.x * w000; ay = v000.y * w000; az = v000.z * w000; aw = v000.w * w000;
        ax = fmaf(v001.x, w001, ax); ay = fmaf(v001.y, w001, ay); az = fmaf(v001.z, w001, az); aw = fmaf(v001.w, w001, aw);
        ax = fmaf(v010.x, w010, ax); ay = fmaf(v010.y, w010, ay); az = fmaf(v010.z, w010, az); aw = fmaf(v010.w, w010, aw);
        ax = fmaf(v011.x, w011, ax); ay = fmaf(v011.y, w011, ay); az = fmaf(v011.z, w011, az); aw = fmaf(v011.w, w011, aw);
        ax = fmaf(v100.x, w100, ax); ay = fmaf(v100.y, w100, ay); az = fmaf(v100.z, w100, az); aw = fmaf(v100.w, w100, aw);
        ax = fmaf(v101.x, w101, ax); ay = fmaf(v101.y, w101, ay); az = fmaf(v101.z, w101, az); aw = fmaf(v101.w, w101, aw);
        ax = fmaf(v110.x, w110, ax); ay = fmaf(v110.y, w110, ay); az = fmaf(v110.z, w110, az); aw = fmaf(v110.w, w110, aw);
        ax = fmaf(v111.x, w111, ax); ay = fmaf(v111.y, w111, ay); az = fmaf(v111.z, w111, az); aw = fmaf(v111.w, w111, aw);
    }

    float4 r;
    r.x = ax * 10.0f;
    r.y = ay * 10.0f;
    r.z = az * 10.0f;
    r.w = aw * 10.0f;
    st_stream(out + (size_t)n * NUM_LEVELS + l, r);   // == out + tid, coalesced
}

extern "C" void kernel_launch(void* const* d_in, const int* in_sizes, int n_in,
                              void* d_out, int out_size)
{
    const float*  x      = (const float*)d_in[0];
    const float4* tables = (const float4*)d_in[1];
    float4*       out    = (float4*)d_out;

    int n_points = in_sizes[0] / 3;
    int total = n_points * NUM_LEVELS;
    int block = 256;
    int grid = (total + block - 1) / block;
    hashenc_kernel<<<grid, block>>>(x, tables, out, n_points);
}